// round 1
// baseline (speedup 1.0000x reference)
#include <cuda_runtime.h>
#include <cuda_bf16.h>
#include <math.h>

// ---------------------------------------------------------------------------
// SchNet interaction block, fused fp32 SIMT baseline.
//
// Inputs (metadata order):
//  0 h        [N,256] f32
//  1 pos      [N,3]   f32
//  2 lin1_w   [256,256]
//  3 lin2_w   [256,256]
//  4 lin2_b   [256]
//  5 mlp_w1   [50,256]
//  6 mlp_b1   [256]
//  7 mlp_w2   [256,256]
//  8 mlp_b2   [256]
//  9 lin_w    [256,256]
// 10 lin_b    [256]
// 11 edge_index [2,E] i32
//
// out: h_update [N,256] (+ pos [N,3] appended if out_size allows)
// ---------------------------------------------------------------------------

#define HID   256
#define NG    50
#define TILE  32
#define SPAD  36          // padded smem stride (floats): bank-friendly, 16B-aligned rows
#define NTHREADS 256

#define CUTOFF_F 10.0f
#define LN2_F    0.69314718055994530942f
#define PI_F     3.14159265358979323846f

#define MAXN 25000
__device__ float g_x[(size_t)MAXN * HID];    // x = h @ lin1_w
__device__ float g_agg[(size_t)MAXN * HID];  // scatter-add target

__device__ __forceinline__ float ssp(float v) {
    // softplus(v) - ln2, numerically stable
    return fmaxf(v, 0.0f) + log1pf(expf(-fabsf(v))) - LN2_F;
}

// ---------------------------------------------------------------------------
// Kernel 1: x = h @ lin1_w   (no bias)
// Block: 32 rows x 256 cols, thread f owns column f for 32 rows.
// ---------------------------------------------------------------------------
__global__ __launch_bounds__(NTHREADS) void node_gemm1(
    const float* __restrict__ h, const float* __restrict__ w,
    float* __restrict__ x, int nnodes)
{
    __shared__ __align__(16) float AT[HID * SPAD];
    const int n0 = blockIdx.x * TILE;
    const int tid = threadIdx.x;

    #pragma unroll 4
    for (int i = 0; i < TILE; i++) {
        int n = n0 + i;
        AT[tid * SPAD + i] = (n < nnodes) ? h[(size_t)n * HID + tid] : 0.0f;
    }
    __syncthreads();

    const int f = tid;
    float acc[TILE];
    #pragma unroll
    for (int e = 0; e < TILE; e++) acc[e] = 0.0f;

    #pragma unroll 4
    for (int k = 0; k < HID; k++) {
        float wv = w[k * HID + f];
        const float4* p = (const float4*)&AT[k * SPAD];
        #pragma unroll
        for (int q = 0; q < TILE / 4; q++) {
            float4 v = p[q];
            acc[4*q+0] = fmaf(v.x, wv, acc[4*q+0]);
            acc[4*q+1] = fmaf(v.y, wv, acc[4*q+1]);
            acc[4*q+2] = fmaf(v.z, wv, acc[4*q+2]);
            acc[4*q+3] = fmaf(v.w, wv, acc[4*q+3]);
        }
    }
    #pragma unroll
    for (int e = 0; e < TILE; e++) {
        int n = n0 + e;
        if (n < nnodes) x[(size_t)n * HID + f] = acc[e];
    }
}

// ---------------------------------------------------------------------------
// Kernel 2 (dominant): fused edge pipeline.
// Per block: 32 edges. dist -> gaussians -> ssp(ea@w1+b1) -> @w2+b2
//           -> * cosine cutoff -> * x[row] -> atomicAdd(agg[col])
// ---------------------------------------------------------------------------
__global__ __launch_bounds__(NTHREADS) void edge_kernel(
    const float* __restrict__ x, const float* __restrict__ pos,
    const int* __restrict__ edge_index,
    const float* __restrict__ w1, const float* __restrict__ b1,
    const float* __restrict__ w2, const float* __restrict__ b2,
    float* __restrict__ agg, int nedges)
{
    __shared__ __align__(16) float eaT[NG * SPAD];   // gaussians, transposed [g][e]
    __shared__ __align__(16) float t1T[HID * SPAD];  // hidden acts, transposed [j][e]
    __shared__ int   row_s[TILE];
    __shared__ int   col_s[TILE];
    __shared__ float C_s[TILE];
    __shared__ float d_s[TILE];

    const int tid = threadIdx.x;
    const int e0  = blockIdx.x * TILE;

    if (tid < TILE) {
        int e = e0 + tid;
        int r = 0, c = 0;
        float d = 0.0f, C = 0.0f;
        if (e < nedges) {
            r = edge_index[e];
            c = edge_index[nedges + e];
            float dx = pos[3*r+0] - pos[3*c+0];
            float dy = pos[3*r+1] - pos[3*c+1];
            float dz = pos[3*r+2] - pos[3*c+2];
            d = sqrtf(dx*dx + dy*dy + dz*dz);
            C = 0.5f * (cosf(d * (PI_F / CUTOFF_F)) + 1.0f);
        }
        row_s[tid] = r; col_s[tid] = c; d_s[tid] = d; C_s[tid] = C;
    }
    __syncthreads();

    // Gaussian smearing, transposed into smem
    const float step  = CUTOFF_F / (float)(NG - 1);
    const float coeff = -0.5f / (step * step);
    for (int idx = tid; idx < TILE * NG; idx += NTHREADS) {
        int e = idx / NG, g = idx % NG;
        float diff = d_s[e] - (float)g * step;
        eaT[g * SPAD + e] = expf(coeff * diff * diff);
    }
    __syncthreads();

    const int f = tid;
    float acc[TILE];

    // ---- GEMM1: t1 = ssp(ea @ w1 + b1) ----
    {
        float bv = b1[f];
        #pragma unroll
        for (int e = 0; e < TILE; e++) acc[e] = bv;
        #pragma unroll 2
        for (int g = 0; g < NG; g++) {
            float wv = w1[g * HID + f];
            const float4* p = (const float4*)&eaT[g * SPAD];
            #pragma unroll
            for (int q = 0; q < TILE / 4; q++) {
                float4 v = p[q];
                acc[4*q+0] = fmaf(v.x, wv, acc[4*q+0]);
                acc[4*q+1] = fmaf(v.y, wv, acc[4*q+1]);
                acc[4*q+2] = fmaf(v.z, wv, acc[4*q+2]);
                acc[4*q+3] = fmaf(v.w, wv, acc[4*q+3]);
            }
        }
        #pragma unroll
        for (int e = 0; e < TILE; e++) t1T[f * SPAD + e] = ssp(acc[e]);
    }
    __syncthreads();

    // ---- GEMM2: W = t1 @ w2 + b2, then cutoff * gather * scatter ----
    {
        float bv = b2[f];
        #pragma unroll
        for (int e = 0; e < TILE; e++) acc[e] = bv;
        #pragma unroll 4
        for (int j = 0; j < HID; j++) {
            float wv = w2[j * HID + f];
            const float4* p = (const float4*)&t1T[j * SPAD];
            #pragma unroll
            for (int q = 0; q < TILE / 4; q++) {
                float4 v = p[q];
                acc[4*q+0] = fmaf(v.x, wv, acc[4*q+0]);
                acc[4*q+1] = fmaf(v.y, wv, acc[4*q+1]);
                acc[4*q+2] = fmaf(v.z, wv, acc[4*q+2]);
                acc[4*q+3] = fmaf(v.w, wv, acc[4*q+3]);
            }
        }
        #pragma unroll
        for (int e = 0; e < TILE; e++) {
            float W   = acc[e] * C_s[e];                       // zero for padded edges
            float msg = x[(size_t)row_s[e] * HID + f] * W;
            atomicAdd(&agg[(size_t)col_s[e] * HID + f], msg);
        }
    }
}

// ---------------------------------------------------------------------------
// Kernel 3: out = ssp(agg @ lin2_w + lin2_b) @ lin_w + lin_b
// Single smem buffer reused between the two GEMMs.
// ---------------------------------------------------------------------------
__global__ __launch_bounds__(NTHREADS) void node_gemm2(
    const float* __restrict__ agg,
    const float* __restrict__ w2, const float* __restrict__ b2,
    const float* __restrict__ w3, const float* __restrict__ b3,
    float* __restrict__ out, int nnodes)
{
    __shared__ __align__(16) float AT[HID * SPAD];
    const int n0 = blockIdx.x * TILE;
    const int tid = threadIdx.x;

    #pragma unroll 4
    for (int i = 0; i < TILE; i++) {
        int n = n0 + i;
        AT[tid * SPAD + i] = (n < nnodes) ? agg[(size_t)n * HID + tid] : 0.0f;
    }
    __syncthreads();

    const int f = tid;
    float acc[TILE];

    // GEMM A: y = ssp(agg @ w2 + b2)
    {
        float bv = b2[f];
        #pragma unroll
        for (int e = 0; e < TILE; e++) acc[e] = bv;
        #pragma unroll 4
        for (int k = 0; k < HID; k++) {
            float wv = w2[k * HID + f];
            const float4* p = (const float4*)&AT[k * SPAD];
            #pragma unroll
            for (int q = 0; q < TILE / 4; q++) {
                float4 v = p[q];
                acc[4*q+0] = fmaf(v.x, wv, acc[4*q+0]);
                acc[4*q+1] = fmaf(v.y, wv, acc[4*q+1]);
                acc[4*q+2] = fmaf(v.z, wv, acc[4*q+2]);
                acc[4*q+3] = fmaf(v.w, wv, acc[4*q+3]);
            }
        }
    }
    __syncthreads();   // everyone done reading AT
    #pragma unroll
    for (int e = 0; e < TILE; e++) AT[f * SPAD + e] = ssp(acc[e]);
    __syncthreads();

    // GEMM B: out = y @ w3 + b3
    {
        float bv = b3[f];
        #pragma unroll
        for (int e = 0; e < TILE; e++) acc[e] = bv;
        #pragma unroll 4
        for (int j = 0; j < HID; j++) {
            float wv = w3[j * HID + f];
            const float4* p = (const float4*)&AT[j * SPAD];
            #pragma unroll
            for (int q = 0; q < TILE / 4; q++) {
                float4 v = p[q];
                acc[4*q+0] = fmaf(v.x, wv, acc[4*q+0]);
                acc[4*q+1] = fmaf(v.y, wv, acc[4*q+1]);
                acc[4*q+2] = fmaf(v.z, wv, acc[4*q+2]);
                acc[4*q+3] = fmaf(v.w, wv, acc[4*q+3]);
            }
        }
        #pragma unroll
        for (int e = 0; e < TILE; e++) {
            int n = n0 + e;
            if (n < nnodes) out[(size_t)n * HID + f] = acc[e];
        }
    }
}

// ---------------------------------------------------------------------------
extern "C" void kernel_launch(void* const* d_in, const int* in_sizes, int n_in,
                              void* d_out, int out_size)
{
    const float* h      = (const float*)d_in[0];
    const float* pos    = (const float*)d_in[1];
    const float* lin1_w = (const float*)d_in[2];
    const float* lin2_w = (const float*)d_in[3];
    const float* lin2_b = (const float*)d_in[4];
    const float* mlp_w1 = (const float*)d_in[5];
    const float* mlp_b1 = (const float*)d_in[6];
    const float* mlp_w2 = (const float*)d_in[7];
    const float* mlp_b2 = (const float*)d_in[8];
    const float* lin_w  = (const float*)d_in[9];
    const float* lin_b  = (const float*)d_in[10];
    const int*   eidx   = (const int*)d_in[11];

    const int nnodes = in_sizes[0] / HID;
    const int nedges = in_sizes[11] / 2;

    float* xbuf = nullptr;
    float* aggb = nullptr;
    cudaGetSymbolAddress((void**)&xbuf, g_x);
    cudaGetSymbolAddress((void**)&aggb, g_agg);

    float* out_f = (float*)d_out;

    cudaMemsetAsync(aggb, 0, (size_t)nnodes * HID * sizeof(float));

    int nblk_nodes = (nnodes + TILE - 1) / TILE;
    int nblk_edges = (nedges + TILE - 1) / TILE;

    node_gemm1<<<nblk_nodes, NTHREADS>>>(h, lin1_w, xbuf, nnodes);
    edge_kernel<<<nblk_edges, NTHREADS>>>(xbuf, pos, eidx,
                                          mlp_w1, mlp_b1, mlp_w2, mlp_b2,
                                          aggb, nedges);
    node_gemm2<<<nblk_nodes, NTHREADS>>>(aggb, lin2_w, lin2_b, lin_w, lin_b,
                                         out_f, nnodes);

    // Append pos if the flattened output includes it.
    if (out_size >= nnodes * HID + nnodes * 3) {
        cudaMemcpyAsync(out_f + (size_t)nnodes * HID, pos,
                        (size_t)nnodes * 3 * sizeof(float),
                        cudaMemcpyDeviceToDevice);
    }
}

// round 3
// speedup vs baseline: 1.0282x; 1.0282x over previous
#include <cuda_runtime.h>
#include <cuda_bf16.h>
#include <math.h>
#include <mma.h>

using namespace nvcuda;

// ---------------------------------------------------------------------------
// SchNet interaction block.
//  - node GEMMs: fp32 SIMT (validated round 1)
//  - edge pipeline: tf32 wmma tensor-core GEMMs + TMA bulk-reduce scatter
// ---------------------------------------------------------------------------

#define HID   256
#define NG    50
#define TILE  32
#define SPAD  36
#define NTHREADS 256

#define CUTOFF_F 10.0f
#define LN2_F    0.69314718055994530942f
#define PI_F     3.14159265358979323846f

#define MAXN 25000
__device__ float g_x[(size_t)MAXN * HID];
__device__ float g_agg[(size_t)MAXN * HID];

__device__ __forceinline__ float ssp(float v) {
    return fmaxf(v, 0.0f) + log1pf(expf(-fabsf(v))) - LN2_F;
}

// cvt.rna.tf32.f32 requires a .b32 destination -> "=r" constraint.
__device__ __forceinline__ float to_tf32(float x) {
    unsigned u;
    asm("cvt.rna.tf32.f32 %0, %1;" : "=r"(u) : "f"(x));
    return __uint_as_float(u);
}

// ---------------------------------------------------------------------------
// Node GEMM 1: x = h @ lin1_w (no bias). fp32 SIMT.
// ---------------------------------------------------------------------------
__global__ __launch_bounds__(NTHREADS) void node_gemm1(
    const float* __restrict__ h, const float* __restrict__ w,
    float* __restrict__ x, int nnodes)
{
    __shared__ __align__(16) float AT[HID * SPAD];
    const int n0 = blockIdx.x * TILE;
    const int tid = threadIdx.x;

    #pragma unroll 4
    for (int i = 0; i < TILE; i++) {
        int n = n0 + i;
        AT[tid * SPAD + i] = (n < nnodes) ? h[(size_t)n * HID + tid] : 0.0f;
    }
    __syncthreads();

    const int f = tid;
    float acc[TILE];
    #pragma unroll
    for (int e = 0; e < TILE; e++) acc[e] = 0.0f;

    #pragma unroll 4
    for (int k = 0; k < HID; k++) {
        float wv = w[k * HID + f];
        const float4* p = (const float4*)&AT[k * SPAD];
        #pragma unroll
        for (int q = 0; q < TILE / 4; q++) {
            float4 v = p[q];
            acc[4*q+0] = fmaf(v.x, wv, acc[4*q+0]);
            acc[4*q+1] = fmaf(v.y, wv, acc[4*q+1]);
            acc[4*q+2] = fmaf(v.z, wv, acc[4*q+2]);
            acc[4*q+3] = fmaf(v.w, wv, acc[4*q+3]);
        }
    }
    #pragma unroll
    for (int e = 0; e < TILE; e++) {
        int n = n0 + e;
        if (n < nnodes) x[(size_t)n * HID + f] = acc[e];
    }
}

// ---------------------------------------------------------------------------
// Edge kernel: tf32 tensor cores + TMA reduce scatter.
//   64 edges per CTA, 256 threads (8 warps), warp w owns cols [w*32, w*32+32).
// ---------------------------------------------------------------------------
#define ET     64         // edges per CTA
#define EA_LD  64         // ea leading dim (floats)
#define K1PAD  56         // gaussian K padded to mult of 8
#define W1_LD  260        // staged w1 leading dim
#define T1_LD  264        // t1C leading dim
#define OFF_EA  0
#define OFF_W1  (ET * EA_LD)                    // 4096
#define OFF_MSG 0
#define UNION_F (OFF_W1 + K1PAD * W1_LD)        // 18656 >= 64*256
#define OFF_T1  UNION_F
#define SMEM_F  (OFF_T1 + ET * T1_LD)
#define SMEM_BYTES (SMEM_F * 4)                 // ~138.9 KB

__global__ __launch_bounds__(NTHREADS) void edge_kernel_tc(
    const float* __restrict__ x, const float* __restrict__ pos,
    const int* __restrict__ edge_index,
    const float* __restrict__ w1, const float* __restrict__ b1,
    const float* __restrict__ w2, const float* __restrict__ b2,
    float* __restrict__ agg, int nedges)
{
    extern __shared__ float sm[];
    float* ea  = sm + OFF_EA;
    float* w1s = sm + OFF_W1;
    float* msg = sm + OFF_MSG;
    float* t1  = sm + OFF_T1;

    __shared__ int   row_s[ET];
    __shared__ int   col_s[ET];
    __shared__ float C_s[ET];
    __shared__ float d_s[ET];

    const int tid  = threadIdx.x;
    const int wid  = tid >> 5;
    const int e0   = blockIdx.x * ET;

    // ---- geometry ----
    if (tid < ET) {
        int e = e0 + tid;
        int r = 0, c = 0;
        float d = 0.0f, C = 0.0f;
        if (e < nedges) {
            r = edge_index[e];
            c = edge_index[nedges + e];
            float dx = pos[3*r+0] - pos[3*c+0];
            float dy = pos[3*r+1] - pos[3*c+1];
            float dz = pos[3*r+2] - pos[3*c+2];
            d = sqrtf(dx*dx + dy*dy + dz*dz);
            C = 0.5f * (cosf(d * (PI_F / CUTOFF_F)) + 1.0f);
        }
        row_s[tid] = r; col_s[tid] = c; d_s[tid] = d; C_s[tid] = C;
    }
    __syncthreads();

    // ---- gaussian smearing into ea [ET][K1PAD], zero-padded K ----
    {
        const float step  = CUTOFF_F / (float)(NG - 1);
        const float coeff = -0.5f / (step * step);
        for (int idx = tid; idx < ET * K1PAD; idx += NTHREADS) {
            int e = idx / K1PAD, g = idx % K1PAD;
            float v = 0.0f;
            if (g < NG) {
                float diff = d_s[e] - (float)g * step;
                v = expf(coeff * diff * diff);
            }
            ea[e * EA_LD + g] = to_tf32(v);
        }
    }

    // ---- stage w1 [K1PAD][256] (rows >= NG zeroed) ----
    #pragma unroll 4
    for (int g = 0; g < K1PAD; g++) {
        float v = (g < NG) ? to_tf32(w1[g * HID + tid]) : 0.0f;
        w1s[g * W1_LD + tid] = v;
    }
    __syncthreads();

    const int cw0 = wid * 32;

    wmma::fragment<wmma::accumulator, 16, 16, 8, float> acc[4][2];

    // ---- GEMM1: t1 = ea @ w1 ----
    #pragma unroll
    for (int mt = 0; mt < 4; mt++)
        #pragma unroll
        for (int nt = 0; nt < 2; nt++)
            wmma::fill_fragment(acc[mt][nt], 0.0f);

    for (int kk = 0; kk < K1PAD / 8; kk++) {
        wmma::fragment<wmma::matrix_b, 16, 16, 8, wmma::precision::tf32, wmma::row_major> bf[2];
        #pragma unroll
        for (int nt = 0; nt < 2; nt++)
            wmma::load_matrix_sync(bf[nt], w1s + kk*8*W1_LD + cw0 + nt*16, W1_LD);
        #pragma unroll
        for (int mt = 0; mt < 4; mt++) {
            wmma::fragment<wmma::matrix_a, 16, 16, 8, wmma::precision::tf32, wmma::row_major> af;
            wmma::load_matrix_sync(af, ea + mt*16*EA_LD + kk*8, EA_LD);
            #pragma unroll
            for (int nt = 0; nt < 2; nt++)
                wmma::mma_sync(acc[mt][nt], af, bf[nt], acc[mt][nt]);
        }
    }
    #pragma unroll
    for (int mt = 0; mt < 4; mt++)
        #pragma unroll
        for (int nt = 0; nt < 2; nt++)
            wmma::store_matrix_sync(t1 + mt*16*T1_LD + cw0 + nt*16, acc[mt][nt],
                                    T1_LD, wmma::mem_row_major);
    __syncthreads();

    // ---- elementwise: t1 = tf32( ssp(t1 + b1) * C ) ----
    {
        float b1v = b1[tid];
        #pragma unroll 4
        for (int i = 0; i < ET; i++) {
            float v = t1[i * T1_LD + tid];
            v = ssp(v + b1v) * C_s[i];
            t1[i * T1_LD + tid] = to_tf32(v);
        }
    }
    __syncthreads();

    // ---- GEMM2: msg = t1C @ w2 ----
    #pragma unroll
    for (int mt = 0; mt < 4; mt++)
        #pragma unroll
        for (int nt = 0; nt < 2; nt++)
            wmma::fill_fragment(acc[mt][nt], 0.0f);

    for (int kk = 0; kk < HID / 8; kk++) {
        wmma::fragment<wmma::matrix_b, 16, 16, 8, wmma::precision::tf32, wmma::row_major> bf[2];
        #pragma unroll
        for (int nt = 0; nt < 2; nt++) {
            wmma::load_matrix_sync(bf[nt], w2 + (size_t)kk*8*HID + cw0 + nt*16, HID);
            #pragma unroll
            for (int t = 0; t < bf[nt].num_elements; t++)
                bf[nt].x[t] = to_tf32(bf[nt].x[t]);
        }
        #pragma unroll
        for (int mt = 0; mt < 4; mt++) {
            wmma::fragment<wmma::matrix_a, 16, 16, 8, wmma::precision::tf32, wmma::row_major> af;
            wmma::load_matrix_sync(af, t1 + mt*16*T1_LD + kk*8, T1_LD);
            #pragma unroll
            for (int nt = 0; nt < 2; nt++)
                wmma::mma_sync(acc[mt][nt], af, bf[nt], acc[mt][nt]);
        }
    }
    // msg overlaps ea/w1s: both dead since the sync before the ssp pass
    #pragma unroll
    for (int mt = 0; mt < 4; mt++)
        #pragma unroll
        for (int nt = 0; nt < 2; nt++)
            wmma::store_matrix_sync(msg + mt*16*HID + cw0 + nt*16, acc[mt][nt],
                                    HID, wmma::mem_row_major);
    __syncthreads();

    // ---- epilogue: msg = x[row] * (msg + b2*C) ----
    {
        float b2v = b2[tid];
        #pragma unroll 4
        for (int i = 0; i < ET; i++) {
            float W = msg[i * HID + tid] + b2v * C_s[i];
            float m = x[(size_t)row_s[i] * HID + tid] * W;
            msg[i * HID + tid] = m;
        }
    }
    __syncthreads();
    asm volatile("fence.proxy.async.shared::cta;" ::: "memory");

    // ---- scatter: one 1KB TMA bulk-reduce per edge ----
    if (tid < ET && (e0 + tid) < nedges) {
        unsigned saddr = (unsigned)__cvta_generic_to_shared(msg + tid * HID);
        float* gdst = agg + (size_t)col_s[tid] * HID;
        asm volatile(
            "cp.reduce.async.bulk.global.shared::cta.bulk_group.add.f32 [%0], [%1], %2;"
            :: "l"(gdst), "r"(saddr), "r"(HID * 4) : "memory");
        asm volatile("cp.async.bulk.commit_group;" ::: "memory");
        asm volatile("cp.async.bulk.wait_group 0;" ::: "memory");
    }
}

// ---------------------------------------------------------------------------
// Node GEMM 2: out = ssp(agg @ lin2_w + lin2_b) @ lin_w + lin_b. fp32 SIMT.
// ---------------------------------------------------------------------------
__global__ __launch_bounds__(NTHREADS) void node_gemm2(
    const float* __restrict__ agg,
    const float* __restrict__ w2, const float* __restrict__ b2,
    const float* __restrict__ w3, const float* __restrict__ b3,
    float* __restrict__ out, int nnodes)
{
    __shared__ __align__(16) float AT[HID * SPAD];
    const int n0 = blockIdx.x * TILE;
    const int tid = threadIdx.x;

    #pragma unroll 4
    for (int i = 0; i < TILE; i++) {
        int n = n0 + i;
        AT[tid * SPAD + i] = (n < nnodes) ? agg[(size_t)n * HID + tid] : 0.0f;
    }
    __syncthreads();

    const int f = tid;
    float acc[TILE];

    {
        float bv = b2[f];
        #pragma unroll
        for (int e = 0; e < TILE; e++) acc[e] = bv;
        #pragma unroll 4
        for (int k = 0; k < HID; k++) {
            float wv = w2[k * HID + f];
            const float4* p = (const float4*)&AT[k * SPAD];
            #pragma unroll
            for (int q = 0; q < TILE / 4; q++) {
                float4 v = p[q];
                acc[4*q+0] = fmaf(v.x, wv, acc[4*q+0]);
                acc[4*q+1] = fmaf(v.y, wv, acc[4*q+1]);
                acc[4*q+2] = fmaf(v.z, wv, acc[4*q+2]);
                acc[4*q+3] = fmaf(v.w, wv, acc[4*q+3]);
            }
        }
    }
    __syncthreads();
    #pragma unroll
    for (int e = 0; e < TILE; e++) AT[f * SPAD + e] = ssp(acc[e]);
    __syncthreads();

    {
        float bv = b3[f];
        #pragma unroll
        for (int e = 0; e < TILE; e++) acc[e] = bv;
        #pragma unroll 4
        for (int j = 0; j < HID; j++) {
            float wv = w3[j * HID + f];
            const float4* p = (const float4*)&AT[j * SPAD];
            #pragma unroll
            for (int q = 0; q < TILE / 4; q++) {
                float4 v = p[q];
                acc[4*q+0] = fmaf(v.x, wv, acc[4*q+0]);
                acc[4*q+1] = fmaf(v.y, wv, acc[4*q+1]);
                acc[4*q+2] = fmaf(v.z, wv, acc[4*q+2]);
                acc[4*q+3] = fmaf(v.w, wv, acc[4*q+3]);
            }
        }
        #pragma unroll
        for (int e = 0; e < TILE; e++) {
            int n = n0 + e;
            if (n < nnodes) out[(size_t)n * HID + f] = acc[e];
        }
    }
}

// ---------------------------------------------------------------------------
extern "C" void kernel_launch(void* const* d_in, const int* in_sizes, int n_in,
                              void* d_out, int out_size)
{
    const float* h      = (const float*)d_in[0];
    const float* pos    = (const float*)d_in[1];
    const float* lin1_w = (const float*)d_in[2];
    const float* lin2_w = (const float*)d_in[3];
    const float* lin2_b = (const float*)d_in[4];
    const float* mlp_w1 = (const float*)d_in[5];
    const float* mlp_b1 = (const float*)d_in[6];
    const float* mlp_w2 = (const float*)d_in[7];
    const float* mlp_b2 = (const float*)d_in[8];
    const float* lin_w  = (const float*)d_in[9];
    const float* lin_b  = (const float*)d_in[10];
    const int*   eidx   = (const int*)d_in[11];

    const int nnodes = in_sizes[0] / HID;
    const int nedges = in_sizes[11] / 2;

    float* xbuf = nullptr;
    float* aggb = nullptr;
    cudaGetSymbolAddress((void**)&xbuf, g_x);
    cudaGetSymbolAddress((void**)&aggb, g_agg);

    float* out_f = (float*)d_out;

    static bool attr_set = false;
    if (!attr_set) {
        cudaFuncSetAttribute(edge_kernel_tc,
                             cudaFuncAttributeMaxDynamicSharedMemorySize,
                             SMEM_BYTES);
        attr_set = true;
    }

    cudaMemsetAsync(aggb, 0, (size_t)nnodes * HID * sizeof(float));

    int nblk_nodes = (nnodes + TILE - 1) / TILE;
    int nblk_edges = (nedges + ET - 1) / ET;

    node_gemm1<<<nblk_nodes, NTHREADS>>>(h, lin1_w, xbuf, nnodes);
    edge_kernel_tc<<<nblk_edges, NTHREADS, SMEM_BYTES>>>(
        xbuf, pos, eidx, mlp_w1, mlp_b1, mlp_w2, mlp_b2, aggb, nedges);
    node_gemm2<<<nblk_nodes, NTHREADS>>>(aggb, lin2_w, lin2_b, lin_w, lin_b,
                                         out_f, nnodes);

    if (out_size >= nnodes * HID + nnodes * 3) {
        cudaMemcpyAsync(out_f + (size_t)nnodes * HID, pos,
                        (size_t)nnodes * 3 * sizeof(float),
                        cudaMemcpyDeviceToDevice);
    }
}

// round 4
// speedup vs baseline: 3.4869x; 3.3913x over previous
#include <cuda_runtime.h>
#include <cuda_bf16.h>
#include <math.h>

// ---------------------------------------------------------------------------
// SchNet interaction block — LUT edge filter.
//
// Insight: the CFConv filter W depends only on scalar distance d. We tabulate
// W(d)·C(d) on an 8192-point grid (fp32 MLP, exact), then each edge does a
// 2-row linear interpolation + x-gather + TMA bulk-reduce scatter. The per-
// edge MLP (97% of round-1 FLOPs) is eliminated.
// ---------------------------------------------------------------------------

#define HID   256
#define NG    50
#define TILE  32
#define SPAD  36
#define NTHREADS 256

#define CUTOFF_F 10.0f
#define LN2_F    0.69314718055994530942f
#define PI_F     3.14159265358979323846f

#define NT    8192                    // table entries
#define DMAX  17.3206f                // > 10*sqrt(3) = max possible distance

#define MAXN 25000
__device__ float g_x[(size_t)MAXN * HID];     // x = h @ lin1_w
__device__ float g_agg[(size_t)MAXN * HID];   // scatter target
__device__ float g_table[(size_t)NT * HID];   // W(d)*C(d) lookup table

__device__ __forceinline__ float ssp(float v) {
    return fmaxf(v, 0.0f) + log1pf(expf(-fabsf(v))) - LN2_F;
}

// ---------------------------------------------------------------------------
// Build LUT: table[t][:] = (ssp(gauss(d_t)@w1+b1)@w2 + b2) * C(d_t),  d_t = t*dx
// 32 rows per CTA, full fp32 (round-1 validated GEMM structure).
// ---------------------------------------------------------------------------
__global__ __launch_bounds__(NTHREADS) void build_table(
    const float* __restrict__ w1, const float* __restrict__ b1,
    const float* __restrict__ w2, const float* __restrict__ b2,
    float* __restrict__ table)
{
    __shared__ __align__(16) float eaT[NG * SPAD];   // gaussians [g][t]
    __shared__ __align__(16) float t1T[HID * SPAD];  // hidden    [j][t]
    __shared__ float C_s[TILE];

    const int tid = threadIdx.x;
    const int t0  = blockIdx.x * TILE;
    const float dx = DMAX / (float)(NT - 1);

    if (tid < TILE) {
        float d = (float)(t0 + tid) * dx;
        C_s[tid] = 0.5f * (cosf(d * (PI_F / CUTOFF_F)) + 1.0f);
    }

    const float step  = CUTOFF_F / (float)(NG - 1);
    const float coeff = -0.5f / (step * step);
    for (int idx = tid; idx < TILE * NG; idx += NTHREADS) {
        int e = idx / NG, g = idx % NG;
        float d = (float)(t0 + e) * dx;
        float diff = d - (float)g * step;
        eaT[g * SPAD + e] = expf(coeff * diff * diff);
    }
    __syncthreads();

    const int f = tid;
    float acc[TILE];

    // t1 = ssp(ea @ w1 + b1)
    {
        float bv = b1[f];
        #pragma unroll
        for (int e = 0; e < TILE; e++) acc[e] = bv;
        #pragma unroll 2
        for (int g = 0; g < NG; g++) {
            float wv = w1[g * HID + f];
            const float4* p = (const float4*)&eaT[g * SPAD];
            #pragma unroll
            for (int q = 0; q < TILE / 4; q++) {
                float4 v = p[q];
                acc[4*q+0] = fmaf(v.x, wv, acc[4*q+0]);
                acc[4*q+1] = fmaf(v.y, wv, acc[4*q+1]);
                acc[4*q+2] = fmaf(v.z, wv, acc[4*q+2]);
                acc[4*q+3] = fmaf(v.w, wv, acc[4*q+3]);
            }
        }
        #pragma unroll
        for (int e = 0; e < TILE; e++) t1T[f * SPAD + e] = ssp(acc[e]);
    }
    __syncthreads();

    // table = (t1 @ w2 + b2) * C
    {
        float bv = b2[f];
        #pragma unroll
        for (int e = 0; e < TILE; e++) acc[e] = bv;
        #pragma unroll 4
        for (int j = 0; j < HID; j++) {
            float wv = w2[j * HID + f];
            const float4* p = (const float4*)&t1T[j * SPAD];
            #pragma unroll
            for (int q = 0; q < TILE / 4; q++) {
                float4 v = p[q];
                acc[4*q+0] = fmaf(v.x, wv, acc[4*q+0]);
                acc[4*q+1] = fmaf(v.y, wv, acc[4*q+1]);
                acc[4*q+2] = fmaf(v.z, wv, acc[4*q+2]);
                acc[4*q+3] = fmaf(v.w, wv, acc[4*q+3]);
            }
        }
        #pragma unroll
        for (int e = 0; e < TILE; e++)
            table[(size_t)(t0 + e) * HID + f] = acc[e] * C_s[e];
    }
}

// ---------------------------------------------------------------------------
// Edge kernel: d -> table lerp -> * x[row] -> TMA bulk-reduce into agg[col]
// 64 edges per CTA, 256 threads. Pure memory pipeline, no MLP.
// ---------------------------------------------------------------------------
#define EB 64
#define EDGE_SMEM_BYTES (EB * HID * 4)   // 64 KB msg buffer

__global__ __launch_bounds__(NTHREADS) void edge_lut_kernel(
    const float* __restrict__ x, const float* __restrict__ pos,
    const int* __restrict__ edge_index,
    const float* __restrict__ table,
    float* __restrict__ agg, int nedges)
{
    extern __shared__ float msg[];       // [EB][HID]
    __shared__ int   row_s[EB];
    __shared__ int   col_s[EB];
    __shared__ int   idx_s[EB];
    __shared__ float u_s[EB];

    const int tid = threadIdx.x;
    const int e0  = blockIdx.x * EB;
    const float inv_dx = (float)(NT - 1) / DMAX;

    if (tid < EB) {
        int e = e0 + tid;
        int r = 0, c = 0, ti = 0;
        float u = 0.0f;
        if (e < nedges) {
            r = edge_index[e];
            c = edge_index[nedges + e];
            float dxp = pos[3*r+0] - pos[3*c+0];
            float dyp = pos[3*r+1] - pos[3*c+1];
            float dzp = pos[3*r+2] - pos[3*c+2];
            float d = sqrtf(dxp*dxp + dyp*dyp + dzp*dzp);
            float s = d * inv_dx;
            ti = (int)s;
            if (ti > NT - 2) ti = NT - 2;
            u = s - (float)ti;
        }
        row_s[tid] = r; col_s[tid] = c; idx_s[tid] = ti; u_s[tid] = u;
    }
    __syncthreads();

    const int f = tid;
    #pragma unroll 8
    for (int i = 0; i < EB; i++) {
        const float* trow = table + (size_t)idx_s[i] * HID + f;
        float ta = trow[0];
        float tb = trow[HID];
        float W  = fmaf(tb - ta, u_s[i], ta);
        float xv = x[(size_t)row_s[i] * HID + f];
        msg[i * HID + f] = xv * W;
    }
    __syncthreads();
    asm volatile("fence.proxy.async.shared::cta;" ::: "memory");

    if (tid < EB && (e0 + tid) < nedges) {
        unsigned saddr = (unsigned)__cvta_generic_to_shared(msg + tid * HID);
        float* gdst = agg + (size_t)col_s[tid] * HID;
        asm volatile(
            "cp.reduce.async.bulk.global.shared::cta.bulk_group.add.f32 [%0], [%1], %2;"
            :: "l"(gdst), "r"(saddr), "r"(HID * 4) : "memory");
        asm volatile("cp.async.bulk.commit_group;" ::: "memory");
        asm volatile("cp.async.bulk.wait_group 0;" ::: "memory");
    }
}

// ---------------------------------------------------------------------------
// Node GEMM 1: x = h @ lin1_w (no bias). fp32 SIMT (validated).
// ---------------------------------------------------------------------------
__global__ __launch_bounds__(NTHREADS) void node_gemm1(
    const float* __restrict__ h, const float* __restrict__ w,
    float* __restrict__ x, int nnodes)
{
    __shared__ __align__(16) float AT[HID * SPAD];
    const int n0 = blockIdx.x * TILE;
    const int tid = threadIdx.x;

    #pragma unroll 4
    for (int i = 0; i < TILE; i++) {
        int n = n0 + i;
        AT[tid * SPAD + i] = (n < nnodes) ? h[(size_t)n * HID + tid] : 0.0f;
    }
    __syncthreads();

    const int f = tid;
    float acc[TILE];
    #pragma unroll
    for (int e = 0; e < TILE; e++) acc[e] = 0.0f;

    #pragma unroll 4
    for (int k = 0; k < HID; k++) {
        float wv = w[k * HID + f];
        const float4* p = (const float4*)&AT[k * SPAD];
        #pragma unroll
        for (int q = 0; q < TILE / 4; q++) {
            float4 v = p[q];
            acc[4*q+0] = fmaf(v.x, wv, acc[4*q+0]);
            acc[4*q+1] = fmaf(v.y, wv, acc[4*q+1]);
            acc[4*q+2] = fmaf(v.z, wv, acc[4*q+2]);
            acc[4*q+3] = fmaf(v.w, wv, acc[4*q+3]);
        }
    }
    #pragma unroll
    for (int e = 0; e < TILE; e++) {
        int n = n0 + e;
        if (n < nnodes) x[(size_t)n * HID + f] = acc[e];
    }
}

// ---------------------------------------------------------------------------
// Node GEMM 2: out = ssp(agg @ lin2_w + lin2_b) @ lin_w + lin_b. fp32 SIMT.
// ---------------------------------------------------------------------------
__global__ __launch_bounds__(NTHREADS) void node_gemm2(
    const float* __restrict__ agg,
    const float* __restrict__ w2, const float* __restrict__ b2,
    const float* __restrict__ w3, const float* __restrict__ b3,
    float* __restrict__ out, int nnodes)
{
    __shared__ __align__(16) float AT[HID * SPAD];
    const int n0 = blockIdx.x * TILE;
    const int tid = threadIdx.x;

    #pragma unroll 4
    for (int i = 0; i < TILE; i++) {
        int n = n0 + i;
        AT[tid * SPAD + i] = (n < nnodes) ? agg[(size_t)n * HID + tid] : 0.0f;
    }
    __syncthreads();

    const int f = tid;
    float acc[TILE];

    {
        float bv = b2[f];
        #pragma unroll
        for (int e = 0; e < TILE; e++) acc[e] = bv;
        #pragma unroll 4
        for (int k = 0; k < HID; k++) {
            float wv = w2[k * HID + f];
            const float4* p = (const float4*)&AT[k * SPAD];
            #pragma unroll
            for (int q = 0; q < TILE / 4; q++) {
                float4 v = p[q];
                acc[4*q+0] = fmaf(v.x, wv, acc[4*q+0]);
                acc[4*q+1] = fmaf(v.y, wv, acc[4*q+1]);
                acc[4*q+2] = fmaf(v.z, wv, acc[4*q+2]);
                acc[4*q+3] = fmaf(v.w, wv, acc[4*q+3]);
            }
        }
    }
    __syncthreads();
    #pragma unroll
    for (int e = 0; e < TILE; e++) AT[f * SPAD + e] = ssp(acc[e]);
    __syncthreads();

    {
        float bv = b3[f];
        #pragma unroll
        for (int e = 0; e < TILE; e++) acc[e] = bv;
        #pragma unroll 4
        for (int j = 0; j < HID; j++) {
            float wv = w3[j * HID + f];
            const float4* p = (const float4*)&AT[j * SPAD];
            #pragma unroll
            for (int q = 0; q < TILE / 4; q++) {
                float4 v = p[q];
                acc[4*q+0] = fmaf(v.x, wv, acc[4*q+0]);
                acc[4*q+1] = fmaf(v.y, wv, acc[4*q+1]);
                acc[4*q+2] = fmaf(v.z, wv, acc[4*q+2]);
                acc[4*q+3] = fmaf(v.w, wv, acc[4*q+3]);
            }
        }
        #pragma unroll
        for (int e = 0; e < TILE; e++) {
            int n = n0 + e;
            if (n < nnodes) out[(size_t)n * HID + f] = acc[e];
        }
    }
}

// ---------------------------------------------------------------------------
extern "C" void kernel_launch(void* const* d_in, const int* in_sizes, int n_in,
                              void* d_out, int out_size)
{
    const float* h      = (const float*)d_in[0];
    const float* pos    = (const float*)d_in[1];
    const float* lin1_w = (const float*)d_in[2];
    const float* lin2_w = (const float*)d_in[3];
    const float* lin2_b = (const float*)d_in[4];
    const float* mlp_w1 = (const float*)d_in[5];
    const float* mlp_b1 = (const float*)d_in[6];
    const float* mlp_w2 = (const float*)d_in[7];
    const float* mlp_b2 = (const float*)d_in[8];
    const float* lin_w  = (const float*)d_in[9];
    const float* lin_b  = (const float*)d_in[10];
    const int*   eidx   = (const int*)d_in[11];

    const int nnodes = in_sizes[0] / HID;
    const int nedges = in_sizes[11] / 2;

    float *xbuf = nullptr, *aggb = nullptr, *tabl = nullptr;
    cudaGetSymbolAddress((void**)&xbuf, g_x);
    cudaGetSymbolAddress((void**)&aggb, g_agg);
    cudaGetSymbolAddress((void**)&tabl, g_table);

    float* out_f = (float*)d_out;

    static bool attr_set = false;
    if (!attr_set) {
        cudaFuncSetAttribute(edge_lut_kernel,
                             cudaFuncAttributeMaxDynamicSharedMemorySize,
                             EDGE_SMEM_BYTES);
        attr_set = true;
    }

    cudaMemsetAsync(aggb, 0, (size_t)nnodes * HID * sizeof(float));

    int nblk_nodes = (nnodes + TILE - 1) / TILE;
    int nblk_edges = (nedges + EB - 1) / EB;

    build_table<<<NT / TILE, NTHREADS>>>(mlp_w1, mlp_b1, mlp_w2, mlp_b2, tabl);
    node_gemm1<<<nblk_nodes, NTHREADS>>>(h, lin1_w, xbuf, nnodes);
    edge_lut_kernel<<<nblk_edges, NTHREADS, EDGE_SMEM_BYTES>>>(
        xbuf, pos, eidx, tabl, aggb, nedges);
    node_gemm2<<<nblk_nodes, NTHREADS>>>(aggb, lin2_w, lin2_b, lin_w, lin_b,
                                         out_f, nnodes);

    if (out_size >= nnodes * HID + nnodes * 3) {
        cudaMemcpyAsync(out_f + (size_t)nnodes * HID, pos,
                        (size_t)nnodes * 3 * sizeof(float),
                        cudaMemcpyDeviceToDevice);
    }
}

// round 6
// speedup vs baseline: 4.8205x; 1.3825x over previous
#include <cuda_runtime.h>
#include <cuda_bf16.h>
#include <math.h>
#include <mma.h>

using namespace nvcuda;

// ---------------------------------------------------------------------------
// SchNet interaction block (sm_100 base target — NO tcgen05 available).
//  - edge filter: distance LUT + lerp + TMA bulk-reduce scatter (round 4)
//  - node GEMMs: tf32 wmma, last two GEMMs fused in one kernel (new)
// ---------------------------------------------------------------------------

#define HID   256
#define NG    50
#define TILE  32
#define SPAD  36
#define NTHREADS 256

#define CUTOFF_F 10.0f
#define LN2_F    0.69314718055994530942f
#define PI_F     3.14159265358979323846f

#define NT    8192
#define DMAX  17.3206f

#define MAXN 25000
__device__ float g_x[(size_t)MAXN * HID];
__device__ float g_agg[(size_t)MAXN * HID];
__device__ float g_table[(size_t)NT * HID];
__device__ float g_wtf[3][HID * HID];        // tf32-rounded weights, [k][n]

__device__ __forceinline__ float ssp(float v) {
    return fmaxf(v, 0.0f) + log1pf(expf(-fabsf(v))) - LN2_F;
}

__device__ __forceinline__ float to_tf32(float x) {
    unsigned u;
    asm("cvt.rna.tf32.f32 %0, %1;" : "=r"(u) : "f"(x));
    return __uint_as_float(u);
}

// ---------------------------------------------------------------------------
// Weight prep: round to tf32 once (layout unchanged: [k][n] row-major).
// ---------------------------------------------------------------------------
__global__ void prep_weights(const float* __restrict__ w0,
                             const float* __restrict__ w1,
                             const float* __restrict__ w2)
{
    int which = blockIdx.y;
    const float* w = (which == 0) ? w0 : (which == 1) ? w1 : w2;
    int k = blockIdx.x;
    int n = threadIdx.x;
    g_wtf[which][k * HID + n] = to_tf32(w[k * HID + n]);
}

// ---------------------------------------------------------------------------
// tf32 wmma node GEMM, optionally fused 2-stage:
//   Y = act1( A @ W1 + b1 );  out = (W2 ? Y @ W2 + b2 : Y)
// CTA: 64 rows x 256 cols. 8 warps as 2x4; warp tile 32x64.
// A staged in smem as tf32 (ld=264). B frags loaded from global tf32 image.
// ---------------------------------------------------------------------------
#define GLD 264
#define NODE_SMEM (64 * GLD * 4)     // 67584 B

__global__ __launch_bounds__(NTHREADS) void node_wmma(
    const float* __restrict__ A,
    const float* __restrict__ W1, const float* __restrict__ b1, int act1,
    const float* __restrict__ W2, const float* __restrict__ b2,
    float* __restrict__ out, int nnodes)
{
    extern __shared__ float buf[];   // [64][GLD]
    const int tid = threadIdx.x;
    const int wid = tid >> 5;
    const int warp_r = wid >> 2;     // 0..1
    const int warp_c = wid & 3;      // 0..3
    const int n0 = blockIdx.x * 64;

    // ---- stage A rows as tf32 ----
    for (int i = tid; i < 64 * 64; i += NTHREADS) {   // 64 rows x 64 float4
        int row = i >> 6, c4 = (i & 63) << 2;
        float4 v = make_float4(0.f, 0.f, 0.f, 0.f);
        if (n0 + row < nnodes)
            v = *(const float4*)(A + (size_t)(n0 + row) * HID + c4);
        buf[row * GLD + c4 + 0] = to_tf32(v.x);
        buf[row * GLD + c4 + 1] = to_tf32(v.y);
        buf[row * GLD + c4 + 2] = to_tf32(v.z);
        buf[row * GLD + c4 + 3] = to_tf32(v.w);
    }
    __syncthreads();

    wmma::fragment<wmma::accumulator, 16, 16, 8, float> acc[2][4];

    // ---- stage 1: A @ W1 ----
    #pragma unroll
    for (int m = 0; m < 2; m++)
        #pragma unroll
        for (int j = 0; j < 4; j++)
            wmma::fill_fragment(acc[m][j], 0.0f);

    #pragma unroll 2
    for (int kk = 0; kk < HID / 8; kk++) {
        wmma::fragment<wmma::matrix_a, 16, 16, 8, wmma::precision::tf32, wmma::row_major> af[2];
        #pragma unroll
        for (int m = 0; m < 2; m++)
            wmma::load_matrix_sync(af[m], buf + (warp_r * 32 + m * 16) * GLD + kk * 8, GLD);
        wmma::fragment<wmma::matrix_b, 16, 16, 8, wmma::precision::tf32, wmma::row_major> bf;
        #pragma unroll
        for (int j = 0; j < 4; j++) {
            wmma::load_matrix_sync(bf, W1 + (size_t)kk * 8 * HID + warp_c * 64 + j * 16, HID);
            #pragma unroll
            for (int m = 0; m < 2; m++)
                wmma::mma_sync(acc[m][j], af[m], bf, acc[m][j]);
        }
    }
    __syncthreads();     // all warps done reading A tile
    #pragma unroll
    for (int m = 0; m < 2; m++)
        #pragma unroll
        for (int j = 0; j < 4; j++)
            wmma::store_matrix_sync(buf + (warp_r * 32 + m * 16) * GLD + warp_c * 64 + j * 16,
                                    acc[m][j], GLD, wmma::mem_row_major);
    __syncthreads();

    if (W2 == nullptr) {
        // single GEMM: epilogue straight to gmem
        float bb = b1 ? b1[tid] : 0.0f;
        #pragma unroll 4
        for (int r = 0; r < 64; r++) {
            if (n0 + r < nnodes) {
                float v = buf[r * GLD + tid] + bb;
                if (act1) v = ssp(v);
                out[(size_t)(n0 + r) * HID + tid] = v;
            }
        }
        return;
    }

    // ---- elementwise between stages: Y = tf32( act1(Y + b1) ) ----
    {
        float bb = b1 ? b1[tid] : 0.0f;
        #pragma unroll 4
        for (int r = 0; r < 64; r++) {
            float v = buf[r * GLD + tid] + bb;
            if (act1) v = ssp(v);
            buf[r * GLD + tid] = to_tf32(v);
        }
    }
    __syncthreads();

    // ---- stage 2: Y @ W2 ----
    #pragma unroll
    for (int m = 0; m < 2; m++)
        #pragma unroll
        for (int j = 0; j < 4; j++)
            wmma::fill_fragment(acc[m][j], 0.0f);

    #pragma unroll 2
    for (int kk = 0; kk < HID / 8; kk++) {
        wmma::fragment<wmma::matrix_a, 16, 16, 8, wmma::precision::tf32, wmma::row_major> af[2];
        #pragma unroll
        for (int m = 0; m < 2; m++)
            wmma::load_matrix_sync(af[m], buf + (warp_r * 32 + m * 16) * GLD + kk * 8, GLD);
        wmma::fragment<wmma::matrix_b, 16, 16, 8, wmma::precision::tf32, wmma::row_major> bf;
        #pragma unroll
        for (int j = 0; j < 4; j++) {
            wmma::load_matrix_sync(bf, W2 + (size_t)kk * 8 * HID + warp_c * 64 + j * 16, HID);
            #pragma unroll
            for (int m = 0; m < 2; m++)
                wmma::mma_sync(acc[m][j], af[m], bf, acc[m][j]);
        }
    }
    __syncthreads();
    #pragma unroll
    for (int m = 0; m < 2; m++)
        #pragma unroll
        for (int j = 0; j < 4; j++)
            wmma::store_matrix_sync(buf + (warp_r * 32 + m * 16) * GLD + warp_c * 64 + j * 16,
                                    acc[m][j], GLD, wmma::mem_row_major);
    __syncthreads();

    {
        float bb = b2 ? b2[tid] : 0.0f;
        #pragma unroll 4
        for (int r = 0; r < 64; r++) {
            if (n0 + r < nnodes)
                out[(size_t)(n0 + r) * HID + tid] = buf[r * GLD + tid] + bb;
        }
    }
}

// ---------------------------------------------------------------------------
// Build LUT (fp32 SIMT, validated): table[t] = (ssp(g(d)@w1+b1)@w2+b2)*C(d)
// ---------------------------------------------------------------------------
__global__ __launch_bounds__(NTHREADS) void build_table(
    const float* __restrict__ w1, const float* __restrict__ b1,
    const float* __restrict__ w2, const float* __restrict__ b2,
    float* __restrict__ table)
{
    __shared__ __align__(16) float eaT[NG * SPAD];
    __shared__ __align__(16) float t1T[HID * SPAD];
    __shared__ float C_s[TILE];

    const int tid = threadIdx.x;
    const int t0  = blockIdx.x * TILE;
    const float dx = DMAX / (float)(NT - 1);

    if (tid < TILE) {
        float d = (float)(t0 + tid) * dx;
        C_s[tid] = 0.5f * (cosf(d * (PI_F / CUTOFF_F)) + 1.0f);
    }

    const float step  = CUTOFF_F / (float)(NG - 1);
    const float coeff = -0.5f / (step * step);
    for (int idx = tid; idx < TILE * NG; idx += NTHREADS) {
        int e = idx / NG, g = idx % NG;
        float d = (float)(t0 + e) * dx;
        float diff = d - (float)g * step;
        eaT[g * SPAD + e] = expf(coeff * diff * diff);
    }
    __syncthreads();

    const int f = tid;
    float acc[TILE];
    {
        float bv = b1[f];
        #pragma unroll
        for (int e = 0; e < TILE; e++) acc[e] = bv;
        #pragma unroll 2
        for (int g = 0; g < NG; g++) {
            float wv = w1[g * HID + f];
            const float4* p = (const float4*)&eaT[g * SPAD];
            #pragma unroll
            for (int q = 0; q < TILE / 4; q++) {
                float4 v = p[q];
                acc[4*q+0] = fmaf(v.x, wv, acc[4*q+0]);
                acc[4*q+1] = fmaf(v.y, wv, acc[4*q+1]);
                acc[4*q+2] = fmaf(v.z, wv, acc[4*q+2]);
                acc[4*q+3] = fmaf(v.w, wv, acc[4*q+3]);
            }
        }
        #pragma unroll
        for (int e = 0; e < TILE; e++) t1T[f * SPAD + e] = ssp(acc[e]);
    }
    __syncthreads();
    {
        float bv = b2[f];
        #pragma unroll
        for (int e = 0; e < TILE; e++) acc[e] = bv;
        #pragma unroll 4
        for (int j = 0; j < HID; j++) {
            float wv = w2[j * HID + f];
            const float4* p = (const float4*)&t1T[j * SPAD];
            #pragma unroll
            for (int q = 0; q < TILE / 4; q++) {
                float4 v = p[q];
                acc[4*q+0] = fmaf(v.x, wv, acc[4*q+0]);
                acc[4*q+1] = fmaf(v.y, wv, acc[4*q+1]);
                acc[4*q+2] = fmaf(v.z, wv, acc[4*q+2]);
                acc[4*q+3] = fmaf(v.w, wv, acc[4*q+3]);
            }
        }
        #pragma unroll
        for (int e = 0; e < TILE; e++)
            table[(size_t)(t0 + e) * HID + f] = acc[e] * C_s[e];
    }
}

// ---------------------------------------------------------------------------
// Edge kernel (round-4 validated): lerp(table) * x[row] -> TMA reduce agg[col]
// ---------------------------------------------------------------------------
#define EB 64
#define EDGE_SMEM_BYTES (EB * HID * 4)

__global__ __launch_bounds__(NTHREADS) void edge_lut_kernel(
    const float* __restrict__ x, const float* __restrict__ pos,
    const int* __restrict__ edge_index,
    const float* __restrict__ table,
    float* __restrict__ agg, int nedges)
{
    extern __shared__ float msg[];
    __shared__ int   row_s[EB];
    __shared__ int   col_s[EB];
    __shared__ int   idx_s[EB];
    __shared__ float u_s[EB];

    const int tid = threadIdx.x;
    const int e0  = blockIdx.x * EB;
    const float inv_dx = (float)(NT - 1) / DMAX;

    if (tid < EB) {
        int e = e0 + tid;
        int r = 0, c = 0, ti = 0;
        float u = 0.0f;
        if (e < nedges) {
            r = edge_index[e];
            c = edge_index[nedges + e];
            float dxp = pos[3*r+0] - pos[3*c+0];
            float dyp = pos[3*r+1] - pos[3*c+1];
            float dzp = pos[3*r+2] - pos[3*c+2];
            float d = sqrtf(dxp*dxp + dyp*dyp + dzp*dzp);
            float s = d * inv_dx;
            ti = (int)s;
            if (ti > NT - 2) ti = NT - 2;
            u = s - (float)ti;
        }
        row_s[tid] = r; col_s[tid] = c; idx_s[tid] = ti; u_s[tid] = u;
    }
    __syncthreads();

    const int f = tid;
    #pragma unroll 8
    for (int i = 0; i < EB; i++) {
        const float* trow = table + (size_t)idx_s[i] * HID + f;
        float ta = trow[0];
        float tbv = trow[HID];
        float W  = fmaf(tbv - ta, u_s[i], ta);
        float xv = x[(size_t)row_s[i] * HID + f];
        msg[i * HID + f] = xv * W;
    }
    __syncthreads();
    asm volatile("fence.proxy.async.shared::cta;" ::: "memory");

    if (tid < EB && (e0 + tid) < nedges) {
        unsigned saddr = (unsigned)__cvta_generic_to_shared(msg + tid * HID);
        float* gdst = agg + (size_t)col_s[tid] * HID;
        asm volatile(
            "cp.reduce.async.bulk.global.shared::cta.bulk_group.add.f32 [%0], [%1], %2;"
            :: "l"(gdst), "r"(saddr), "r"(HID * 4) : "memory");
        asm volatile("cp.async.bulk.commit_group;" ::: "memory");
        asm volatile("cp.async.bulk.wait_group 0;" ::: "memory");
    }
}

// ---------------------------------------------------------------------------
extern "C" void kernel_launch(void* const* d_in, const int* in_sizes, int n_in,
                              void* d_out, int out_size)
{
    const float* h      = (const float*)d_in[0];
    const float* pos    = (const float*)d_in[1];
    const float* lin1_w = (const float*)d_in[2];
    const float* lin2_w = (const float*)d_in[3];
    const float* lin2_b = (const float*)d_in[4];
    const float* mlp_w1 = (const float*)d_in[5];
    const float* mlp_b1 = (const float*)d_in[6];
    const float* mlp_w2 = (const float*)d_in[7];
    const float* mlp_b2 = (const float*)d_in[8];
    const float* lin_w  = (const float*)d_in[9];
    const float* lin_b  = (const float*)d_in[10];
    const int*   eidx   = (const int*)d_in[11];

    const int nnodes = in_sizes[0] / HID;
    const int nedges = in_sizes[11] / 2;

    float *xbuf = nullptr, *aggb = nullptr, *tabl = nullptr, *wtf = nullptr;
    cudaGetSymbolAddress((void**)&xbuf, g_x);
    cudaGetSymbolAddress((void**)&aggb, g_agg);
    cudaGetSymbolAddress((void**)&tabl, g_table);
    cudaGetSymbolAddress((void**)&wtf, g_wtf);

    float* out_f = (float*)d_out;

    static bool attr_set = false;
    if (!attr_set) {
        cudaFuncSetAttribute(edge_lut_kernel,
                             cudaFuncAttributeMaxDynamicSharedMemorySize,
                             EDGE_SMEM_BYTES);
        cudaFuncSetAttribute(node_wmma,
                             cudaFuncAttributeMaxDynamicSharedMemorySize,
                             NODE_SMEM);
        attr_set = true;
    }

    cudaMemsetAsync(aggb, 0, (size_t)nnodes * HID * sizeof(float));

    const int nblk_wmma  = (nnodes + 63) / 64;
    const int nblk_edges = (nedges + EB - 1) / EB;

    prep_weights<<<dim3(HID, 3), HID>>>(lin1_w, lin2_w, lin_w);
    build_table<<<NT / TILE, NTHREADS>>>(mlp_w1, mlp_b1, mlp_w2, mlp_b2, tabl);

    // x = h @ lin1_w  (no bias, no act)
    node_wmma<<<nblk_wmma, NTHREADS, NODE_SMEM>>>(
        h, wtf + 0 * HID * HID, nullptr, 0, nullptr, nullptr, xbuf, nnodes);

    edge_lut_kernel<<<nblk_edges, NTHREADS, EDGE_SMEM_BYTES>>>(
        xbuf, pos, eidx, tabl, aggb, nedges);

    // out = ssp(agg @ lin2_w + lin2_b) @ lin_w + lin_b   (fused)
    node_wmma<<<nblk_wmma, NTHREADS, NODE_SMEM>>>(
        aggb, wtf + 1 * HID * HID, lin2_b, 1,
        wtf + 2 * HID * HID, lin_b, out_f, nnodes);

    if (out_size >= nnodes * HID + nnodes * 3) {
        cudaMemcpyAsync(out_f + (size_t)nnodes * HID, pos,
                        (size_t)nnodes * 3 * sizeof(float),
                        cudaMemcpyDeviceToDevice);
    }
}

// round 7
// speedup vs baseline: 6.4358x; 1.3351x over previous
#include <cuda_runtime.h>
#include <cuda_bf16.h>
#include <math.h>
#include <mma.h>

using namespace nvcuda;

// ---------------------------------------------------------------------------
// SchNet interaction block (sm_100 base target — no tcgen05).
//  - edge filter: distance LUT (4096 pts) + float4 lerp + TMA bulk-reduce
//  - node GEMMs: tf32 wmma; last two GEMMs fused
// ---------------------------------------------------------------------------

#define HID   256
#define NG    50
#define TILE  32
#define SPAD  36
#define NTHREADS 256

#define CUTOFF_F 10.0f
#define LN2_F    0.69314718055994530942f
#define PI_F     3.14159265358979323846f

#define NT    4096
#define DMAX  17.3206f

#define MAXN 25000
__device__ float g_x[(size_t)MAXN * HID];
__device__ float g_agg[(size_t)MAXN * HID];
__device__ float g_table[(size_t)NT * HID];
__device__ float g_wtf[3][HID * HID];        // tf32-rounded weights, [k][n]

__device__ __forceinline__ float ssp(float v) {
    return fmaxf(v, 0.0f) + log1pf(expf(-fabsf(v))) - LN2_F;
}

__device__ __forceinline__ float to_tf32(float x) {
    unsigned u;
    asm("cvt.rna.tf32.f32 %0, %1;" : "=r"(u) : "f"(x));
    return __uint_as_float(u);
}

// ---------------------------------------------------------------------------
__global__ void prep_weights(const float* __restrict__ w0,
                             const float* __restrict__ w1,
                             const float* __restrict__ w2)
{
    int which = blockIdx.y;
    const float* w = (which == 0) ? w0 : (which == 1) ? w1 : w2;
    int k = blockIdx.x;
    int n = threadIdx.x;
    g_wtf[which][k * HID + n] = to_tf32(w[k * HID + n]);
}

// ---------------------------------------------------------------------------
// tf32 wmma node GEMM, optionally fused 2-stage (validated round 6).
// ---------------------------------------------------------------------------
#define GLD 264
#define NODE_SMEM (64 * GLD * 4)

__global__ __launch_bounds__(NTHREADS) void node_wmma(
    const float* __restrict__ A,
    const float* __restrict__ W1, const float* __restrict__ b1, int act1,
    const float* __restrict__ W2, const float* __restrict__ b2,
    float* __restrict__ out, int nnodes)
{
    extern __shared__ float buf[];
    const int tid = threadIdx.x;
    const int wid = tid >> 5;
    const int warp_r = wid >> 2;
    const int warp_c = wid & 3;
    const int n0 = blockIdx.x * 64;

    for (int i = tid; i < 64 * 64; i += NTHREADS) {
        int row = i >> 6, c4 = (i & 63) << 2;
        float4 v = make_float4(0.f, 0.f, 0.f, 0.f);
        if (n0 + row < nnodes)
            v = *(const float4*)(A + (size_t)(n0 + row) * HID + c4);
        buf[row * GLD + c4 + 0] = to_tf32(v.x);
        buf[row * GLD + c4 + 1] = to_tf32(v.y);
        buf[row * GLD + c4 + 2] = to_tf32(v.z);
        buf[row * GLD + c4 + 3] = to_tf32(v.w);
    }
    __syncthreads();

    wmma::fragment<wmma::accumulator, 16, 16, 8, float> acc[2][4];

    #pragma unroll
    for (int m = 0; m < 2; m++)
        #pragma unroll
        for (int j = 0; j < 4; j++)
            wmma::fill_fragment(acc[m][j], 0.0f);

    #pragma unroll 2
    for (int kk = 0; kk < HID / 8; kk++) {
        wmma::fragment<wmma::matrix_a, 16, 16, 8, wmma::precision::tf32, wmma::row_major> af[2];
        #pragma unroll
        for (int m = 0; m < 2; m++)
            wmma::load_matrix_sync(af[m], buf + (warp_r * 32 + m * 16) * GLD + kk * 8, GLD);
        wmma::fragment<wmma::matrix_b, 16, 16, 8, wmma::precision::tf32, wmma::row_major> bf;
        #pragma unroll
        for (int j = 0; j < 4; j++) {
            wmma::load_matrix_sync(bf, W1 + (size_t)kk * 8 * HID + warp_c * 64 + j * 16, HID);
            #pragma unroll
            for (int m = 0; m < 2; m++)
                wmma::mma_sync(acc[m][j], af[m], bf, acc[m][j]);
        }
    }
    __syncthreads();
    #pragma unroll
    for (int m = 0; m < 2; m++)
        #pragma unroll
        for (int j = 0; j < 4; j++)
            wmma::store_matrix_sync(buf + (warp_r * 32 + m * 16) * GLD + warp_c * 64 + j * 16,
                                    acc[m][j], GLD, wmma::mem_row_major);
    __syncthreads();

    if (W2 == nullptr) {
        float bb = b1 ? b1[tid] : 0.0f;
        #pragma unroll 4
        for (int r = 0; r < 64; r++) {
            if (n0 + r < nnodes) {
                float v = buf[r * GLD + tid] + bb;
                if (act1) v = ssp(v);
                out[(size_t)(n0 + r) * HID + tid] = v;
            }
        }
        return;
    }

    {
        float bb = b1 ? b1[tid] : 0.0f;
        #pragma unroll 4
        for (int r = 0; r < 64; r++) {
            float v = buf[r * GLD + tid] + bb;
            if (act1) v = ssp(v);
            buf[r * GLD + tid] = to_tf32(v);
        }
    }
    __syncthreads();

    #pragma unroll
    for (int m = 0; m < 2; m++)
        #pragma unroll
        for (int j = 0; j < 4; j++)
            wmma::fill_fragment(acc[m][j], 0.0f);

    #pragma unroll 2
    for (int kk = 0; kk < HID / 8; kk++) {
        wmma::fragment<wmma::matrix_a, 16, 16, 8, wmma::precision::tf32, wmma::row_major> af[2];
        #pragma unroll
        for (int m = 0; m < 2; m++)
            wmma::load_matrix_sync(af[m], buf + (warp_r * 32 + m * 16) * GLD + kk * 8, GLD);
        wmma::fragment<wmma::matrix_b, 16, 16, 8, wmma::precision::tf32, wmma::row_major> bf;
        #pragma unroll
        for (int j = 0; j < 4; j++) {
            wmma::load_matrix_sync(bf, W2 + (size_t)kk * 8 * HID + warp_c * 64 + j * 16, HID);
            #pragma unroll
            for (int m = 0; m < 2; m++)
                wmma::mma_sync(acc[m][j], af[m], bf, acc[m][j]);
        }
    }
    __syncthreads();
    #pragma unroll
    for (int m = 0; m < 2; m++)
        #pragma unroll
        for (int j = 0; j < 4; j++)
            wmma::store_matrix_sync(buf + (warp_r * 32 + m * 16) * GLD + warp_c * 64 + j * 16,
                                    acc[m][j], GLD, wmma::mem_row_major);
    __syncthreads();

    {
        float bb = b2 ? b2[tid] : 0.0f;
        #pragma unroll 4
        for (int r = 0; r < 64; r++) {
            if (n0 + r < nnodes)
                out[(size_t)(n0 + r) * HID + tid] = buf[r * GLD + tid] + bb;
        }
    }
}

// ---------------------------------------------------------------------------
// Build LUT (fp32 SIMT, validated)
// ---------------------------------------------------------------------------
__global__ __launch_bounds__(NTHREADS) void build_table(
    const float* __restrict__ w1, const float* __restrict__ b1,
    const float* __restrict__ w2, const float* __restrict__ b2,
    float* __restrict__ table)
{
    __shared__ __align__(16) float eaT[NG * SPAD];
    __shared__ __align__(16) float t1T[HID * SPAD];
    __shared__ float C_s[TILE];

    const int tid = threadIdx.x;
    const int t0  = blockIdx.x * TILE;
    const float dx = DMAX / (float)(NT - 1);

    if (tid < TILE) {
        float d = (float)(t0 + tid) * dx;
        C_s[tid] = 0.5f * (cosf(d * (PI_F / CUTOFF_F)) + 1.0f);
    }

    const float step  = CUTOFF_F / (float)(NG - 1);
    const float coeff = -0.5f / (step * step);
    for (int idx = tid; idx < TILE * NG; idx += NTHREADS) {
        int e = idx / NG, g = idx % NG;
        float d = (float)(t0 + e) * dx;
        float diff = d - (float)g * step;
        eaT[g * SPAD + e] = expf(coeff * diff * diff);
    }
    __syncthreads();

    const int f = tid;
    float acc[TILE];
    {
        float bv = b1[f];
        #pragma unroll
        for (int e = 0; e < TILE; e++) acc[e] = bv;
        #pragma unroll 2
        for (int g = 0; g < NG; g++) {
            float wv = w1[g * HID + f];
            const float4* p = (const float4*)&eaT[g * SPAD];
            #pragma unroll
            for (int q = 0; q < TILE / 4; q++) {
                float4 v = p[q];
                acc[4*q+0] = fmaf(v.x, wv, acc[4*q+0]);
                acc[4*q+1] = fmaf(v.y, wv, acc[4*q+1]);
                acc[4*q+2] = fmaf(v.z, wv, acc[4*q+2]);
                acc[4*q+3] = fmaf(v.w, wv, acc[4*q+3]);
            }
        }
        #pragma unroll
        for (int e = 0; e < TILE; e++) t1T[f * SPAD + e] = ssp(acc[e]);
    }
    __syncthreads();
    {
        float bv = b2[f];
        #pragma unroll
        for (int e = 0; e < TILE; e++) acc[e] = bv;
        #pragma unroll 4
        for (int j = 0; j < HID; j++) {
            float wv = w2[j * HID + f];
            const float4* p = (const float4*)&t1T[j * SPAD];
            #pragma unroll
            for (int q = 0; q < TILE / 4; q++) {
                float4 v = p[q];
                acc[4*q+0] = fmaf(v.x, wv, acc[4*q+0]);
                acc[4*q+1] = fmaf(v.y, wv, acc[4*q+1]);
                acc[4*q+2] = fmaf(v.z, wv, acc[4*q+2]);
                acc[4*q+3] = fmaf(v.w, wv, acc[4*q+3]);
            }
        }
        #pragma unroll
        for (int e = 0; e < TILE; e++)
            table[(size_t)(t0 + e) * HID + f] = acc[e] * C_s[e];
    }
}

// ---------------------------------------------------------------------------
// Edge kernel v2: float4-vectorized, EB=32 for occupancy.
//   grp = tid>>6 handles edges grp, grp+4, ... ; lane4 = tid&63 is float4 col.
// ---------------------------------------------------------------------------
#define EB 32
#define EDGE_SMEM_BYTES (EB * HID * 4)   // 32 KB

__global__ __launch_bounds__(NTHREADS) void edge_lut_kernel(
    const float* __restrict__ x, const float* __restrict__ pos,
    const int* __restrict__ edge_index,
    const float* __restrict__ table,
    float* __restrict__ agg, int nedges)
{
    extern __shared__ float msg[];       // [EB][HID]
    __shared__ int   row_s[EB];
    __shared__ int   col_s[EB];
    __shared__ int   idx_s[EB];
    __shared__ float u_s[EB];

    const int tid   = threadIdx.x;
    const int grp   = tid >> 6;          // 0..3
    const int lane4 = tid & 63;          // float4 column
    const int e0    = blockIdx.x * EB;
    const float inv_dx = (float)(NT - 1) / DMAX;

    if (tid < EB) {
        int e = e0 + tid;
        int r = 0, c = 0, ti = 0;
        float u = 0.0f;
        if (e < nedges) {
            r = edge_index[e];
            c = edge_index[nedges + e];
            float dxp = pos[3*r+0] - pos[3*c+0];
            float dyp = pos[3*r+1] - pos[3*c+1];
            float dzp = pos[3*r+2] - pos[3*c+2];
            float d = sqrtf(dxp*dxp + dyp*dyp + dzp*dzp);
            float s = d * inv_dx;
            ti = (int)s;
            if (ti > NT - 2) ti = NT - 2;
            u = s - (float)ti;
        }
        row_s[tid] = r; col_s[tid] = c; idx_s[tid] = ti; u_s[tid] = u;
    }
    __syncthreads();

    #pragma unroll
    for (int it = 0; it < EB / 4; it++) {
        int i = grp + it * 4;
        const float4* trow = (const float4*)(table + (size_t)idx_s[i] * HID) + lane4;
        float4 a  = trow[0];
        float4 b  = trow[HID / 4];
        float  u  = u_s[i];
        float4 xv = ((const float4*)(x + (size_t)row_s[i] * HID))[lane4];
        float4 m;
        m.x = xv.x * fmaf(b.x - a.x, u, a.x);
        m.y = xv.y * fmaf(b.y - a.y, u, a.y);
        m.z = xv.z * fmaf(b.z - a.z, u, a.z);
        m.w = xv.w * fmaf(b.w - a.w, u, a.w);
        ((float4*)(msg + i * HID))[lane4] = m;
    }
    __syncthreads();
    asm volatile("fence.proxy.async.shared::cta;" ::: "memory");

    if (tid < EB && (e0 + tid) < nedges) {
        unsigned saddr = (unsigned)__cvta_generic_to_shared(msg + tid * HID);
        float* gdst = agg + (size_t)col_s[tid] * HID;
        asm volatile(
            "cp.reduce.async.bulk.global.shared::cta.bulk_group.add.f32 [%0], [%1], %2;"
            :: "l"(gdst), "r"(saddr), "r"(HID * 4) : "memory");
        asm volatile("cp.async.bulk.commit_group;" ::: "memory");
        asm volatile("cp.async.bulk.wait_group 0;" ::: "memory");
    }
}

// ---------------------------------------------------------------------------
extern "C" void kernel_launch(void* const* d_in, const int* in_sizes, int n_in,
                              void* d_out, int out_size)
{
    const float* h      = (const float*)d_in[0];
    const float* pos    = (const float*)d_in[1];
    const float* lin1_w = (const float*)d_in[2];
    const float* lin2_w = (const float*)d_in[3];
    const float* lin2_b = (const float*)d_in[4];
    const float* mlp_w1 = (const float*)d_in[5];
    const float* mlp_b1 = (const float*)d_in[6];
    const float* mlp_w2 = (const float*)d_in[7];
    const float* mlp_b2 = (const float*)d_in[8];
    const float* lin_w  = (const float*)d_in[9];
    const float* lin_b  = (const float*)d_in[10];
    const int*   eidx   = (const int*)d_in[11];

    const int nnodes = in_sizes[0] / HID;
    const int nedges = in_sizes[11] / 2;

    float *xbuf = nullptr, *aggb = nullptr, *tabl = nullptr, *wtf = nullptr;
    cudaGetSymbolAddress((void**)&xbuf, g_x);
    cudaGetSymbolAddress((void**)&aggb, g_agg);
    cudaGetSymbolAddress((void**)&tabl, g_table);
    cudaGetSymbolAddress((void**)&wtf, g_wtf);

    float* out_f = (float*)d_out;

    static bool attr_set = false;
    if (!attr_set) {
        cudaFuncSetAttribute(edge_lut_kernel,
                             cudaFuncAttributeMaxDynamicSharedMemorySize,
                             EDGE_SMEM_BYTES);
        cudaFuncSetAttribute(node_wmma,
                             cudaFuncAttributeMaxDynamicSharedMemorySize,
                             NODE_SMEM);
        attr_set = true;
    }

    cudaMemsetAsync(aggb, 0, (size_t)nnodes * HID * sizeof(float));

    const int nblk_wmma  = (nnodes + 63) / 64;
    const int nblk_edges = (nedges + EB - 1) / EB;

    prep_weights<<<dim3(HID, 3), HID>>>(lin1_w, lin2_w, lin_w);
    build_table<<<NT / TILE, NTHREADS>>>(mlp_w1, mlp_b1, mlp_w2, mlp_b2, tabl);

    node_wmma<<<nblk_wmma, NTHREADS, NODE_SMEM>>>(
        h, wtf + 0 * HID * HID, nullptr, 0, nullptr, nullptr, xbuf, nnodes);

    edge_lut_kernel<<<nblk_edges, NTHREADS, EDGE_SMEM_BYTES>>>(
        xbuf, pos, eidx, tabl, aggb, nedges);

    node_wmma<<<nblk_wmma, NTHREADS, NODE_SMEM>>>(
        aggb, wtf + 1 * HID * HID, lin2_b, 1,
        wtf + 2 * HID * HID, lin_b, out_f, nnodes);

    if (out_size >= nnodes * HID + nnodes * 3) {
        cudaMemcpyAsync(out_f + (size_t)nnodes * HID, pos,
                        (size_t)nnodes * 3 * sizeof(float),
                        cudaMemcpyDeviceToDevice);
    }
}